// round 4
// baseline (speedup 1.0000x reference)
#include <cuda_runtime.h>
#include <cstdint>

#define CHN 128
#define HH  128
#define WW  128
#define TH  4            // output rows per block
#define CSPLIT 2
#define CPB 64           // channels per block
#define TROWS 8          // TH + 4 halo rows
#define TPITCH 136       // floats per smem tile row (cols -2..129 at idx 2..133 -> col j at idx j+4)
#define NSTAGE 3

// ---- packed f32x2 helpers (Blackwell PTX) ----
__device__ __forceinline__ unsigned long long pack2(float lo, float hi) {
    unsigned long long r;
    asm("mov.b64 %0, {%1, %2};" : "=l"(r) : "f"(lo), "f"(hi));
    return r;
}
__device__ __forceinline__ void unpack2(unsigned long long v, float& lo, float& hi) {
    asm("mov.b64 {%0, %1}, %2;" : "=f"(lo), "=f"(hi) : "l"(v));
}
__device__ __forceinline__ unsigned long long mul2(unsigned long long a, unsigned long long b) {
    unsigned long long d;
    asm("mul.rn.f32x2 %0, %1, %2;" : "=l"(d) : "l"(a), "l"(b));
    return d;
}
__device__ __forceinline__ unsigned long long fma2(unsigned long long a, unsigned long long b, unsigned long long c) {
    unsigned long long d;
    asm("fma.rn.f32x2 %0, %1, %2, %3;" : "=l"(d) : "l"(a), "l"(b), "l"(c));
    return d;
}
__device__ __forceinline__ unsigned long long add2(unsigned long long a, unsigned long long b) {
    unsigned long long d;
    asm("add.rn.f32x2 %0, %1, %2;" : "=l"(d) : "l"(a), "l"(b));
    return d;
}

__device__ __forceinline__ void cp_async16(float* sdst, const float* gsrc) {
    uint32_t d = (uint32_t)__cvta_generic_to_shared(sdst);
    asm volatile("cp.async.cg.shared.global [%0], [%1], 16;" :: "r"(d), "l"(gsrc));
}
__device__ __forceinline__ void cp_async4(float* sdst, const float* gsrc) {
    uint32_t d = (uint32_t)__cvta_generic_to_shared(sdst);
    asm volatile("cp.async.ca.shared.global [%0], [%1], 4;" :: "r"(d), "l"(gsrc));
}

// Stage one channel's 8-row x tile (with horizontal halo) into smem via cp.async.
__device__ __forceinline__ void load_tile(float* sbuf, const float* xc, int h0, int tid) {
    // interior: row k = tid/32, lane covers 4 cols -> idx 4+4*lane (16B aligned)
    int k = tid >> 5, lane = tid & 31;
    int r = h0 - 2 + k; r = r < 0 ? 0 : (r > HH - 1 ? HH - 1 : r);
    cp_async16(sbuf + k * TPITCH + 4 + 4 * lane, xc + r * WW + 4 * lane);
    // halo: 4 floats per row (cols -2,-1,128,129 -> idx 2,3,132,133), values clamped (masked by kk)
    if (tid < 32) {
        int k2 = tid >> 2, e = tid & 3;
        int r2 = h0 - 2 + k2; r2 = r2 < 0 ? 0 : (r2 > HH - 1 ? HH - 1 : r2);
        int idx    = (e < 2) ? (2 + e) : (130 + e);
        int colimg = (e < 2) ? 0 : (WW - 1);
        cp_async4(sbuf + k2 * TPITCH + idx, xc + r2 * WW + colimg);
    }
}

__global__ __launch_bounds__(256, 2)
void dwconv_ksa_kernel(const float* __restrict__ x,
                       const float* __restrict__ ksa,
                       const float* __restrict__ w,
                       const float* __restrict__ b,
                       float* __restrict__ out)
{
    __shared__ float tiles[NSTAGE][TROWS * TPITCH];   // 3 * 8*136*4 = 13056 B
    __shared__ float2 ws2[CPB * 25];                  // broadcast {w,w} pairs, 12800 B
    __shared__ float  bs[CPB];

    const int tx = threadIdx.x;          // 0..63 -> w-pair
    const int ty = threadIdx.y;          // 0..3
    const int tid = ty * 64 + tx;
    const int h0 = blockIdx.x * TH;
    const int n  = blockIdx.y;
    const int c0 = blockIdx.z * CPB;

    const float* xn = x + (size_t)(n * CHN + c0) * HH * WW;

    // prologue: start prefetch of first NSTAGE-1 tiles immediately
    #pragma unroll
    for (int s = 0; s < NSTAGE - 1; ++s) {
        load_tile(tiles[s], xn + (size_t)s * HH * WW, h0, tid);
        asm volatile("cp.async.commit_group;");
    }

    // fill broadcast weight pairs + bias (overlaps prefetch)
    for (int i = tid; i < CPB * 25; i += 256) {
        float wv = w[c0 * 25 + i];
        ws2[i] = make_float2(wv, wv);
    }
    if (tid < CPB) bs[tid] = b[c0 + tid];

    const int h  = h0 + ty;
    const int w0 = tx * 2;

    // ---- ksa for this pixel pair -> registers, boundary masks folded in ----
    unsigned long long kk2[25];
    const float* ksabase = ksa + ((size_t)(n * 25) * HH + h) * WW + w0;
    #pragma unroll
    for (int t = 0; t < 25; t++) {
        float2 v = *(const float2*)(ksabase + (size_t)t * HH * WW);
        const int i = t / 5, j = t % 5;
        const int r = h + i - 2;
        const bool rok = (r >= 0) && (r < HH);
        const int cA = w0 + j - 2;
        const int cB = cA + 1;
        v.x = (rok && cA >= 0 && cA < WW) ? v.x : 0.0f;
        v.y = (rok && cB >= 0 && cB < WW) ? v.y : 0.0f;
        kk2[t] = pack2(v.x, v.y);
    }

    float* outp = out + ((size_t)(n * CHN + c0) * HH + h) * WW + w0;

    for (int cl = 0; cl < CPB; ++cl) {
        __syncthreads();   // all threads done reading the buffer we're about to overwrite
        if (cl + NSTAGE - 1 < CPB)
            load_tile(tiles[(cl + NSTAGE - 1) % NSTAGE],
                      xn + (size_t)(cl + NSTAGE - 1) * HH * WW, h0, tid);
        asm volatile("cp.async.commit_group;");
        asm volatile("cp.async.wait_group %0;" :: "n"(NSTAGE - 2));
        __syncthreads();   // tile cl visible to all threads

        const float* sb = tiles[cl % NSTAGE];
        const unsigned long long* wq = (const unsigned long long*)ws2 + cl * 25;

        unsigned long long accA = 0ULL;   // taps 0,2,4  (bit pattern 0 == {0.f,0.f})
        unsigned long long accB = 0ULL;   // taps 1,3

        #pragma unroll
        for (int i = 0; i < 5; i++) {
            const float* row = sb + (ty + i) * TPITCH + w0;
            const float2 A = *(const float2*)(row + 2);   // x[w0-2], x[w0-1]
            const float2 B = *(const float2*)(row + 4);   // x[w0  ], x[w0+1]
            const float2 C = *(const float2*)(row + 6);   // x[w0+2], x[w0+3]
            unsigned long long p0 = pack2(A.x, A.y);
            unsigned long long p1 = pack2(A.y, B.x);
            unsigned long long p2 = pack2(B.x, B.y);
            unsigned long long p3 = pack2(B.y, C.x);
            unsigned long long p4 = pack2(C.x, C.y);
            accA = fma2(mul2(kk2[i*5+0], wq[i*5+0]), p0, accA);
            accB = fma2(mul2(kk2[i*5+1], wq[i*5+1]), p1, accB);
            accA = fma2(mul2(kk2[i*5+2], wq[i*5+2]), p2, accA);
            accB = fma2(mul2(kk2[i*5+3], wq[i*5+3]), p3, accB);
            accA = fma2(mul2(kk2[i*5+4], wq[i*5+4]), p4, accA);
        }

        unsigned long long acc = add2(accA, accB);
        float a0, a1;
        unpack2(acc, a0, a1);
        const float bb = bs[cl];
        float2 o;
        o.x = a0 + bb;
        o.y = a1 + bb;
        *(float2*)(outp + (size_t)cl * HH * WW) = o;
    }
}

extern "C" void kernel_launch(void* const* d_in, const int* in_sizes, int n_in,
                              void* d_out, int out_size)
{
    const float* x   = (const float*)d_in[0];
    const float* ksa = (const float*)d_in[1];
    const float* w   = (const float*)d_in[2];
    const float* b   = (const float*)d_in[3];
    float* out = (float*)d_out;

    const int n_batch = in_sizes[0] / (CHN * HH * WW);   // 4

    dim3 block(64, TH);
    dim3 grid(HH / TH, n_batch, CSPLIT);
    dwconv_ksa_kernel<<<grid, block>>>(x, ksa, w, b, out);
}

// round 5
// speedup vs baseline: 1.1412x; 1.1412x over previous
#include <cuda_runtime.h>
#include <cstdint>

#define CHN 128
#define HH  128
#define WW  128
#define TH  4
#define CSPLIT 2
#define CPB 64

typedef unsigned long long ull;

__device__ __forceinline__ ull pack2(float lo, float hi) {
    ull r; asm("mov.b64 %0, {%1, %2};" : "=l"(r) : "f"(lo), "f"(hi)); return r;
}
__device__ __forceinline__ void unpack2(ull v, float& lo, float& hi) {
    asm("mov.b64 {%0, %1}, %2;" : "=f"(lo), "=f"(hi) : "l"(v));
}
__device__ __forceinline__ ull mul2(ull a, ull b) {
    ull d; asm("mul.rn.f32x2 %0, %1, %2;" : "=l"(d) : "l"(a), "l"(b)); return d;
}
__device__ __forceinline__ ull fma2(ull a, ull b, ull c) {
    ull d; asm("fma.rn.f32x2 %0, %1, %2, %3;" : "=l"(d) : "l"(a), "l"(b), "l"(c)); return d;
}
__device__ __forceinline__ ull add2(ull a, ull b) {
    ull d; asm("add.rn.f32x2 %0, %1, %2;" : "=l"(d) : "l"(a), "l"(b)); return d;
}

__global__ __launch_bounds__(256, 2)
void dwconv_ksa_kernel(const float* __restrict__ x,
                       const float* __restrict__ ksa,
                       const float* __restrict__ w,
                       const float* __restrict__ b,
                       float* __restrict__ out)
{
    // grid: (H/TH, N, CSPLIT); block: (64, TH)
    const int tx = threadIdx.x;            // 0..63 -> w-pair
    const int ty = threadIdx.y;            // 0..3
    const int tid = ty * 64 + tx;
    const int h0 = blockIdx.x * TH;
    const int n  = blockIdx.y;
    const int c0 = blockIdx.z * CPB;

    __shared__ float2 ws2[CPB * 25];       // {w,w} duplicated pairs (12.8 KB)
    __shared__ float2 bs2[CPB];            // {b,b}

    for (int i = tid; i < CPB * 25; i += 256) {
        float wv = w[c0 * 25 + i];
        ws2[i] = make_float2(wv, wv);
    }
    if (tid < CPB) {
        float bv = b[c0 + tid];
        bs2[tid] = make_float2(bv, bv);
    }

    const int h  = h0 + ty;
    const int w0 = tx * 2;

    // ---- ksa for this pixel pair -> packed registers, boundary masks folded ----
    ull kk2[25];
    const float* ksabase = ksa + ((size_t)(n * 25) * HH + h) * WW + w0;
    #pragma unroll
    for (int t = 0; t < 25; t++) {
        float2 v = *(const float2*)(ksabase + (size_t)t * HH * WW);
        const int i = t / 5, j = t % 5;
        const int r = h + i - 2;
        const bool rok = (r >= 0) && (r < HH);
        const int cA = w0 + j - 2;
        const int cB = cA + 1;
        v.x = (rok && cA >= 0 && cA < WW) ? v.x : 0.0f;
        v.y = (rok && cB >= 0 && cB < WW) ? v.y : 0.0f;
        kk2[t] = pack2(v.x, v.y);
    }

    // clamped row offsets (garbage rows masked by kk==0)
    int rowoff[5];
    #pragma unroll
    for (int i = 0; i < 5; i++) {
        int r = h + i - 2;
        r = r < 0 ? 0 : (r > HH - 1 ? HH - 1 : r);
        rowoff[i] = r * WW;
    }
    const int e0 = (w0 - 2 < 0) ? 0 : (w0 - 2);
    const int e2 = (w0 + 2 > WW - 2) ? (WW - 2) : (w0 + 2);

    __syncthreads();

    const float* xn   = x   + (size_t)(n * CHN + c0) * HH * WW;
    float*       outp = out + ((size_t)(n * CHN + c0) * HH + h) * WW + w0;

    // 2 channels per iteration: independent load/FMA chains for ILP/MLP
    #pragma unroll 1
    for (int cp = 0; cp < CPB / 2; ++cp) {
        const int ca = 2 * cp;
        const float* xa = xn + (size_t)ca * HH * WW;
        const float* xb = xa + HH * WW;
        const ull* wqa = (const ull*)ws2 + ca * 25;
        const ull* wqb = wqa + 25;

        ull aA = *((const ull*)bs2 + ca);      // acc init = {bias,bias}
        ull aB = 0ULL;
        ull bA = *((const ull*)bs2 + ca + 1);
        ull bB = 0ULL;

        #pragma unroll
        for (int i = 0; i < 5; i++) {
            const float* ra = xa + rowoff[i];
            const float* rb = xb + rowoff[i];
            const float2 A0 = *(const float2*)(ra + e0);
            const float2 B0 = *(const float2*)(ra + w0);
            const float2 C0 = *(const float2*)(ra + e2);
            const float2 A1 = *(const float2*)(rb + e0);
            const float2 B1 = *(const float2*)(rb + w0);
            const float2 C1 = *(const float2*)(rb + e2);

            const ull q00 = pack2(A0.x, A0.y);
            const ull q01 = pack2(A0.y, B0.x);
            const ull q02 = pack2(B0.x, B0.y);
            const ull q03 = pack2(B0.y, C0.x);
            const ull q04 = pack2(C0.x, C0.y);
            const ull q10 = pack2(A1.x, A1.y);
            const ull q11 = pack2(A1.y, B1.x);
            const ull q12 = pack2(B1.x, B1.y);
            const ull q13 = pack2(B1.y, C1.x);
            const ull q14 = pack2(C1.x, C1.y);

            aA = fma2(mul2(kk2[i*5+0], wqa[i*5+0]), q00, aA);
            bA = fma2(mul2(kk2[i*5+0], wqb[i*5+0]), q10, bA);
            aB = fma2(mul2(kk2[i*5+1], wqa[i*5+1]), q01, aB);
            bB = fma2(mul2(kk2[i*5+1], wqb[i*5+1]), q11, bB);
            aA = fma2(mul2(kk2[i*5+2], wqa[i*5+2]), q02, aA);
            bA = fma2(mul2(kk2[i*5+2], wqb[i*5+2]), q12, bA);
            aB = fma2(mul2(kk2[i*5+3], wqa[i*5+3]), q03, aB);
            bB = fma2(mul2(kk2[i*5+3], wqb[i*5+3]), q13, bB);
            aA = fma2(mul2(kk2[i*5+4], wqa[i*5+4]), q04, aA);
            bA = fma2(mul2(kk2[i*5+4], wqb[i*5+4]), q14, bA);
        }

        ull ra = add2(aA, aB);
        ull rb = add2(bA, bB);
        float a0, a1, b0v, b1v;
        unpack2(ra, a0, a1);
        unpack2(rb, b0v, b1v);
        *(float2*)(outp + (size_t)ca * HH * WW)       = make_float2(a0, a1);
        *(float2*)(outp + (size_t)(ca + 1) * HH * WW) = make_float2(b0v, b1v);
    }
}

extern "C" void kernel_launch(void* const* d_in, const int* in_sizes, int n_in,
                              void* d_out, int out_size)
{
    const float* x   = (const float*)d_in[0];
    const float* ksa = (const float*)d_in[1];
    const float* w   = (const float*)d_in[2];
    const float* b   = (const float*)d_in[3];
    float* out = (float*)d_out;

    const int n_batch = in_sizes[0] / (CHN * HH * WW);   // 4

    dim3 block(64, TH);
    dim3 grid(HH / TH, n_batch, CSPLIT);
    dwconv_ksa_kernel<<<grid, block>>>(x, ksa, w, b, out);
}